// round 14
// baseline (speedup 1.0000x reference)
#include <cuda_runtime.h>
#include <cuda_bf16.h>
#include <cstdint>

typedef unsigned long long ull;
typedef __nv_bfloat16 bf16;

#define NB    16
#define NPTS  512
#define BNT   (NB*NPTS)   // 8192
#define KNN   8
#define SEQ   12
#define HALF  6

// ---------------------------------------------------------------------------
// Scratch (static device globals).  Z buffers double-buffered by step parity.
// ---------------------------------------------------------------------------
__device__ __align__(16) bf16 g_f1h[2 * BNT * 64],  g_f1l[2 * BNT * 64];
__device__ __align__(16) bf16 g_f2h[2 * BNT * 128], g_f2l[2 * BNT * 128];
__device__ __align__(16) bf16 g_f3h[2 * BNT * 256], g_f3l[2 * BNT * 256];
__device__ __align__(16) float g_Z1[2 * BNT * 64];
__device__ __align__(16) float g_Z2[2 * BNT * 128];
__device__ __align__(16) float g_Z3[2 * BNT * 256];
// 8 slots: 0..6 = precomputed warmup topk, 7 = dynamic (steps 7..11)
__device__ __align__(16) int   g_idx[8 * BNT * KNN];
__device__ __align__(16) float g_d2 [8 * BNT * KNN];
__device__ __align__(16) bf16 g_Wn1h[64*64],   g_Wn1l[64*64];
__device__ __align__(16) bf16 g_Wn2h[128*128], g_Wn2l[128*128];
__device__ __align__(16) bf16 g_Wn3h[256*256], g_Wn3l[256*256];
__device__ __align__(16) bf16 g_Wf3h[128*256], g_Wf3l[128*256];
__device__ __align__(16) bf16 g_Wmh [256*64],  g_Wml [256*64];

// ---------------------------------------------------------------------------
// helpers
// ---------------------------------------------------------------------------
__device__ __forceinline__ void ffma2(ull& d, ull a, ull b)
{
    asm("fma.rn.f32x2 %0, %1, %2, %0;" : "+l"(d) : "l"(a), "l"(b));
}
__device__ __forceinline__ float2 unpk(ull v)
{
    float2 f;
    asm("mov.b64 {%0, %1}, %2;" : "=f"(f.x), "=f"(f.y) : "l"(v));
    return f;
}
__device__ __forceinline__ uint32_t smem_u32(const void* p)
{
    uint32_t a;
    asm("{ .reg .u64 t; cvta.to.shared.u64 t, %1; cvt.u32.u64 %0, t; }"
        : "=r"(a) : "l"(p));
    return a;
}
__device__ __forceinline__ void ldsm4(uint32_t* r, uint32_t a)
{
    asm volatile("ldmatrix.sync.aligned.m8n8.x4.shared.b16 {%0,%1,%2,%3}, [%4];"
        : "=r"(r[0]), "=r"(r[1]), "=r"(r[2]), "=r"(r[3]) : "r"(a));
}
__device__ __forceinline__ void ldsm4t(uint32_t* r, uint32_t a)
{
    asm volatile("ldmatrix.sync.aligned.m8n8.x4.trans.shared.b16 {%0,%1,%2,%3}, [%4];"
        : "=r"(r[0]), "=r"(r[1]), "=r"(r[2]), "=r"(r[3]) : "r"(a));
}
__device__ __forceinline__ void mma16816(float* d, const uint32_t* a,
                                         uint32_t b0, uint32_t b1)
{
    asm volatile(
        "mma.sync.aligned.m16n8k16.row.col.f32.bf16.bf16.f32 "
        "{%0,%1,%2,%3}, {%4,%5,%6,%7}, {%8,%9}, {%0,%1,%2,%3};"
        : "+f"(d[0]), "+f"(d[1]), "+f"(d[2]), "+f"(d[3])
        : "r"(a[0]), "r"(a[1]), "r"(a[2]), "r"(a[3]), "r"(b0), "r"(b1));
}
__device__ __forceinline__ void cp16(uint32_t dst, const void* src)
{
    asm volatile("cp.async.cg.shared.global [%0], [%1], 16;"
                 :: "r"(dst), "l"(src));
}
__device__ __forceinline__ void cp_commit()
{
    asm volatile("cp.async.commit_group;");
}
template<int N>
__device__ __forceinline__ void cp_wait()
{
    asm volatile("cp.async.wait_group %0;" :: "n"(N));
}
__device__ __forceinline__ void pack_store(bf16* H, bf16* L, size_t off,
                                           float ox, float oy)
{
    bf16 hx = __float2bfloat16_rn(ox);
    bf16 hy = __float2bfloat16_rn(oy);
    bf16 lx = __float2bfloat16_rn(ox - __bfloat162float(hx));
    bf16 ly = __float2bfloat16_rn(oy - __bfloat162float(hy));
    uint32_t ph = (uint32_t)*reinterpret_cast<uint16_t*>(&hx)
                | ((uint32_t)*reinterpret_cast<uint16_t*>(&hy) << 16);
    uint32_t pl = (uint32_t)*reinterpret_cast<uint16_t*>(&lx)
                | ((uint32_t)*reinterpret_cast<uint16_t*>(&ly) << 16);
    *reinterpret_cast<uint32_t*>(H + off) = ph;
    *reinterpret_cast<uint32_t*>(L + off) = pl;
}

// ---------------------------------------------------------------------------
// init: zero states + weight hi/lo splits
// ---------------------------------------------------------------------------
__device__ __forceinline__ void wsplit(const float* W, bf16* hi, bf16* lo,
                                       int total, int i0, int stride)
{
    for (int i = i0; i < total; i += stride) {
        float x = W[i];
        bf16 h = __float2bfloat16_rn(x);
        bf16 l = __float2bfloat16_rn(x - __bfloat162float(h));
        hi[i] = h;
        lo[i] = l;
    }
}

__global__ void init_kernel(const float* __restrict__ Wn1,
                            const float* __restrict__ Wn2,
                            const float* __restrict__ Wn3,
                            const float* __restrict__ Wf3,
                            const float* __restrict__ Wm)
{
    int stride = gridDim.x * blockDim.x;
    int i0 = blockIdx.x * blockDim.x + threadIdx.x;
    uint32_t* a;
    a = reinterpret_cast<uint32_t*>(g_f1h);
    for (int i = i0; i < BNT * 64;  i += stride) a[i] = 0u;
    a = reinterpret_cast<uint32_t*>(g_f1l);
    for (int i = i0; i < BNT * 64;  i += stride) a[i] = 0u;
    a = reinterpret_cast<uint32_t*>(g_f2h);
    for (int i = i0; i < BNT * 128; i += stride) a[i] = 0u;
    a = reinterpret_cast<uint32_t*>(g_f2l);
    for (int i = i0; i < BNT * 128; i += stride) a[i] = 0u;
    a = reinterpret_cast<uint32_t*>(g_f3h);
    for (int i = i0; i < BNT * 256; i += stride) a[i] = 0u;
    a = reinterpret_cast<uint32_t*>(g_f3l);
    for (int i = i0; i < BNT * 256; i += stride) a[i] = 0u;

    wsplit(Wn1, g_Wn1h, g_Wn1l, 64*64,   i0, stride);
    wsplit(Wn2, g_Wn2h, g_Wn2l, 128*128, i0, stride);
    wsplit(Wn3, g_Wn3h, g_Wn3l, 256*256, i0, stride);
    wsplit(Wf3, g_Wf3h, g_Wf3l, 128*256, i0, stride);
    wsplit(Wm,  g_Wmh,  g_Wml,  256*64,  i0, stride);
}

__global__ void noop_kernel() {}

// ---------------------------------------------------------------------------
// 128x64 HMMA tile, 4 warps, warp tile 32m x 64n, split-bf16, BK=32,
// double-buffered cp.async.
// MODE 0: plain fp32 store. MODE 1: +s.Wd epilogue (Z). MODE 2: fused MLP.
// MODE 3: fused combine3 (o = b3 + acc - q.Wd3 + max_k Z3[row_k]) -> bf16.
// ---------------------------------------------------------------------------
#define BUFSZ   29696
#define DSMEM   (2 * BUFSZ)     // 59392

template<int MODE>
__device__ __forceinline__ void gemm_tile(
    char* sm, int tid,
    const bf16* __restrict__ Ah, const bf16* __restrict__ Al,
    const bf16* __restrict__ Bh, const bf16* __restrict__ Bl,
    float* __restrict__ C, int N, int K, int rowBase, int nStrip,
    const float* sxyz, int sbs, const float* Wfull,      // MODE 1
    const float* bm, const float* Wl, const float* bl,   // MODE 2
    const float* cur, int cbs, float* dst, int dbs,      // MODE 2
    const float* Z3, const float* b3,                    // MODE 3
    const int* idx, const float* d2, float r2,           // MODE 3
    bf16* outH, bf16* outL)                              // MODE 3
{
    int warp = tid >> 5, lane = tid & 31;

    float acc[2][8][4];
    #pragma unroll
    for (int mg = 0; mg < 2; mg++)
        #pragma unroll
        for (int i = 0; i < 8; i++)
            #pragma unroll
            for (int j = 0; j < 4; j++) acc[mg][i][j] = 0.f;

    uint32_t smBase = smem_u32(sm);

    auto stage = [&](int buf, int k0) {
        uint32_t base = smBase + buf * BUFSZ;
        #pragma unroll
        for (int i = 0; i < 4; i++) {
            int c = tid + i * 128;
            int row = c >> 2, col8 = (c & 3) * 8;
            uint32_t d = base + row * 80 + col8 * 2;
            const bf16* sh = Ah + (size_t)(rowBase + row) * K + k0 + col8;
            const bf16* sl = Al + (size_t)(rowBase + row) * K + k0 + col8;
            cp16(d,         sh);
            cp16(d + 10240, sl);
        }
        #pragma unroll
        for (int i = 0; i < 2; i++) {
            int c = tid + i * 128;
            int row = c >> 3, col8 = (c & 7) * 8;
            uint32_t d = base + 20480 + row * 144 + col8 * 2;
            const bf16* sh = Bh + (size_t)(k0 + row) * N + nStrip + col8;
            const bf16* sl = Bl + (size_t)(k0 + row) * N + nStrip + col8;
            cp16(d,        sh);
            cp16(d + 4608, sl);
        }
        cp_commit();
    };

    int nT = K >> 5;
    stage(0, 0);

    int aLane = lane & 15;
    int hi8   = (lane >> 4) * 8;
    int bRow  = lane & 15;

    for (int it = 0; it < nT; it++) {
        int buf = it & 1;
        if (it + 1 < nT) { stage(buf ^ 1, (it + 1) * 32); cp_wait<1>(); }
        else             { cp_wait<0>(); }
        __syncthreads();

        uint32_t base = smBase + buf * BUFSZ;
        #pragma unroll
        for (int kk = 0; kk < 32; kk += 16) {
            uint32_t ah[2][4], al[2][4];
            #pragma unroll
            for (int mg = 0; mg < 2; mg++) {
                int row = warp * 32 + mg * 16 + aLane;
                uint32_t ad = base + row * 80 + (kk + hi8) * 2;
                ldsm4(ah[mg], ad);
                ldsm4(al[mg], ad + 10240);
            }
            #pragma unroll
            for (int np = 0; np < 4; np++) {
                uint32_t bd = base + 20480 + (kk + bRow) * 144 + (np * 16 + hi8) * 2;
                uint32_t bh[4], bl2[4];
                ldsm4t(bh,  bd);
                ldsm4t(bl2, bd + 4608);
                #pragma unroll
                for (int mg = 0; mg < 2; mg++) {
                    mma16816(acc[mg][np*2],     ah[mg], bh[0], bh[1]);
                    mma16816(acc[mg][np*2],     ah[mg], bl2[0], bl2[1]);
                    mma16816(acc[mg][np*2],     al[mg], bh[0], bh[1]);
                    mma16816(acc[mg][np*2 + 1], ah[mg], bh[2], bh[3]);
                    mma16816(acc[mg][np*2 + 1], ah[mg], bl2[2], bl2[3]);
                    mma16816(acc[mg][np*2 + 1], al[mg], bh[2], bh[3]);
                }
            }
        }
        __syncthreads();
    }

    int g = lane >> 2, tg = lane & 3;
    if constexpr (MODE == 0) {
        #pragma unroll
        for (int mg = 0; mg < 2; mg++) {
            float* Crow = C + (size_t)(rowBase + warp * 32 + mg * 16 + g) * N
                        + nStrip + tg * 2;
            #pragma unroll
            for (int ng = 0; ng < 8; ng++) {
                *reinterpret_cast<float2*>(Crow + ng * 8) =
                    make_float2(acc[mg][ng][0], acc[mg][ng][1]);
                *reinterpret_cast<float2*>(Crow + (size_t)8 * N + ng * 8) =
                    make_float2(acc[mg][ng][2], acc[mg][ng][3]);
            }
        }
    } else if constexpr (MODE == 1) {
        #pragma unroll
        for (int mg = 0; mg < 2; mg++) {
            int p0_ = rowBase + warp * 32 + mg * 16 + g;
            int p1_ = p0_ + 8;
            int b0 = p0_ >> 9, n0 = p0_ & 511, n1 = p1_ & 511;
            const float* sp0 = sxyz + b0 * sbs + n0 * 3;
            const float* sp1 = sxyz + b0 * sbs + n1 * 3;
            float s00 = sp0[0], s01 = sp0[1], s02 = sp0[2];
            float s10 = sp1[0], s11 = sp1[1], s12 = sp1[2];
            float* Crow = C + (size_t)p0_ * N + nStrip + tg * 2;
            #pragma unroll
            for (int ng = 0; ng < 8; ng++) {
                int col = nStrip + ng * 8 + tg * 2;
                float w00 = __ldg(Wfull + col),         w01 = __ldg(Wfull + col + 1);
                float w10 = __ldg(Wfull + N + col),     w11 = __ldg(Wfull + N + col + 1);
                float w20 = __ldg(Wfull + 2 * N + col), w21 = __ldg(Wfull + 2 * N + col + 1);
                float a0 = s00 * w00 + s01 * w10 + s02 * w20;
                float a1 = s00 * w01 + s01 * w11 + s02 * w21;
                float c0 = s10 * w00 + s11 * w10 + s12 * w20;
                float c1 = s10 * w01 + s11 * w11 + s12 * w21;
                *reinterpret_cast<float2*>(Crow + ng * 8) =
                    make_float2(acc[mg][ng][0] + a0, acc[mg][ng][1] + a1);
                *reinterpret_cast<float2*>(Crow + (size_t)8 * N + ng * 8) =
                    make_float2(acc[mg][ng][2] + c0, acc[mg][ng][3] + c1);
            }
        }
    } else if constexpr (MODE == 2) {
        #pragma unroll
        for (int mg = 0; mg < 2; mg++) {
            float m0[3] = {0, 0, 0}, m1[3] = {0, 0, 0};
            #pragma unroll
            for (int ng = 0; ng < 8; ng++) {
                int j0 = ng * 8 + tg * 2;
                float h00 = fmaxf(acc[mg][ng][0] + __ldg(bm + j0),     0.f);
                float h01 = fmaxf(acc[mg][ng][1] + __ldg(bm + j0 + 1), 0.f);
                float h10 = fmaxf(acc[mg][ng][2] + __ldg(bm + j0),     0.f);
                float h11 = fmaxf(acc[mg][ng][3] + __ldg(bm + j0 + 1), 0.f);
                #pragma unroll
                for (int d = 0; d < 3; d++) {
                    float w0 = __ldg(Wl + j0 * 3 + d);
                    float w1 = __ldg(Wl + (j0 + 1) * 3 + d);
                    m0[d] += h00 * w0 + h01 * w1;
                    m1[d] += h10 * w0 + h11 * w1;
                }
            }
            #pragma unroll
            for (int d = 0; d < 3; d++) {
                m0[d] += __shfl_xor_sync(0xFFFFFFFFu, m0[d], 1);
                m0[d] += __shfl_xor_sync(0xFFFFFFFFu, m0[d], 2);
                m1[d] += __shfl_xor_sync(0xFFFFFFFFu, m1[d], 1);
                m1[d] += __shfl_xor_sync(0xFFFFFFFFu, m1[d], 2);
            }
            if (tg == 0) {
                int p0_ = rowBase + warp * 32 + mg * 16 + g;
                #pragma unroll
                for (int r = 0; r < 2; r++) {
                    int p_ = p0_ + r * 8;
                    int b = p_ >> 9, n = p_ & 511;
                    const float* cp = cur + b * cbs + n * 3;
                    float*       dp = dst + b * dbs + n * 3;
                    float* mm = r ? m1 : m0;
                    #pragma unroll
                    for (int d = 0; d < 3; d++)
                        dp[d] = cp[d] + __ldg(bl + d) + mm[d];
                }
            }
        }
    } else {
        // MODE 3: fused combine3. acc = Q3 tile. N = 256.
        #pragma unroll
        for (int mg = 0; mg < 2; mg++) {
            #pragma unroll
            for (int r = 0; r < 2; r++) {
                int p = rowBase + warp * 32 + mg * 16 + g + r * 8;
                int b = p >> 9, n = p & 511;
                // effective neighbor rows for this point
                int rows[KNN];
                int i0 = __ldg(idx + (size_t)p * KNN);
                #pragma unroll
                for (int k = 0; k < KNN; k++) {
                    int raw = __ldg(idx + (size_t)p * KNN + k);
                    float dd = __ldg(d2 + (size_t)p * KNN + k);
                    rows[k] = b * NPTS + ((dd <= r2) ? raw : i0);
                }
                const float* qp = cur + b * cbs + n * 3;
                float q0 = qp[0], q1 = qp[1], q2v = qp[2];
                #pragma unroll
                for (int ng = 0; ng < 8; ng++) {
                    int col = nStrip + ng * 8 + tg * 2;
                    float w00 = __ldg(Wfull + col),         w01 = __ldg(Wfull + col + 1);
                    float w10 = __ldg(Wfull + 256 + col),   w11 = __ldg(Wfull + 256 + col + 1);
                    float w20 = __ldg(Wfull + 512 + col),   w21 = __ldg(Wfull + 512 + col + 1);
                    float tx = q0 * w00 + q1 * w10 + q2v * w20;
                    float ty = q0 * w01 + q1 * w11 + q2v * w21;
                    float mx = -3.4e38f, my = -3.4e38f;
                    #pragma unroll
                    for (int k = 0; k < KNN; k++) {
                        float2 zf = unpk(__ldg(reinterpret_cast<const ull*>(
                            Z3 + (size_t)rows[k] * 256 + col)));
                        mx = fmaxf(mx, zf.x);
                        my = fmaxf(my, zf.y);
                    }
                    float qa = (r == 0) ? acc[mg][ng][0] : acc[mg][ng][2];
                    float qb = (r == 0) ? acc[mg][ng][1] : acc[mg][ng][3];
                    float ox = __ldg(b3 + col)     + qa + (mx - tx);
                    float oy = __ldg(b3 + col + 1) + qb + (my - ty);
                    pack_store(outH, outL, (size_t)p * 256 + col, ox, oy);
                }
            }
        }
    }
}

// ---------------------------------------------------------------------------
// Z GEMM kernels (side stream): Z = f_in @ Wn + s.Wd  (parity pointer passed)
// ---------------------------------------------------------------------------
__global__ __launch_bounds__(128) void z12_kernel(
    const bf16* f1h, const bf16* f1l, const bf16* f2h, const bf16* f2l,
    const float* __restrict__ W1, const float* __restrict__ W2,
    const float* __restrict__ s, int sbs,
    float* __restrict__ Z1, float* __restrict__ Z2)
{
    extern __shared__ __align__(16) char sm[];
    if (blockIdx.y == 0) {
        gemm_tile<1>(sm, threadIdx.x, f1h, f1l, g_Wn1h, g_Wn1l, Z1,
                     64, 64, blockIdx.x * 128, 0,
                     s, sbs, W1, nullptr, nullptr, nullptr,
                     nullptr, 0, nullptr, 0,
                     nullptr, nullptr, nullptr, nullptr, 0.f, nullptr, nullptr);
    } else {
        gemm_tile<1>(sm, threadIdx.x, f2h, f2l, g_Wn2h, g_Wn2l, Z2,
                     128, 128, blockIdx.x * 128, (blockIdx.y - 1) * 64,
                     s, sbs, W2, nullptr, nullptr, nullptr,
                     nullptr, 0, nullptr, 0,
                     nullptr, nullptr, nullptr, nullptr, 0.f, nullptr, nullptr);
    }
}

__global__ __launch_bounds__(128) void z3_kernel(
    const bf16* f3h, const bf16* f3l,
    const float* __restrict__ W3,
    const float* __restrict__ s, int sbs,
    float* __restrict__ Z3)
{
    extern __shared__ __align__(16) char sm[];
    gemm_tile<1>(sm, threadIdx.x, f3h, f3l, g_Wn3h, g_Wn3l, Z3,
                 256, 256, blockIdx.x * 128, blockIdx.y * 64,
                 s, sbs, W3, nullptr, nullptr, nullptr,
                 nullptr, 0, nullptr, 0,
                 nullptr, nullptr, nullptr, nullptr, 0.f, nullptr, nullptr);
}

// Q3 GEMM + fused combine3 -> f3o (bf16 hi/lo)
__global__ __launch_bounds__(128) void q3c3_kernel(
    const bf16* f2oh, const bf16* f2ol,
    const float* __restrict__ Z3,
    const float* __restrict__ W3, const float* __restrict__ b3,
    const int* __restrict__ idx, const float* __restrict__ d2,
    const float* __restrict__ q, int qbs, float r2,
    bf16* __restrict__ f3oh, bf16* __restrict__ f3ol)
{
    extern __shared__ __align__(16) char sm[];
    gemm_tile<3>(sm, threadIdx.x, f2oh, f2ol, g_Wf3h, g_Wf3l, nullptr,
                 256, 128, blockIdx.x * 128, blockIdx.y * 64,
                 nullptr, 0, W3, nullptr, nullptr, nullptr,
                 q, qbs, nullptr, 0,
                 Z3, b3, idx, d2, r2, f3oh, f3ol);
}

__global__ __launch_bounds__(128) void hmma_mlp_kernel(
    const bf16* Ah, const bf16* Al, const bf16* Bh, const bf16* Bl, int K,
    const float* bm, const float* Wl, const float* bl,
    const float* cur, int cbs, float* dst, int dbs)
{
    extern __shared__ __align__(16) char sm[];
    gemm_tile<2>(sm, threadIdx.x, Ah, Al, Bh, Bl, nullptr, 64, K,
                 blockIdx.x * 128, 0,
                 nullptr, 0, nullptr, bm, Wl, bl, cur, cbs, dst, dbs,
                 nullptr, nullptr, nullptr, nullptr, 0.f, nullptr, nullptr);
}

// ---------------------------------------------------------------------------
// top-8 body (validated)
// ---------------------------------------------------------------------------
__device__ __forceinline__ void topk_body(
    const float* __restrict__ q, int qbs,
    const float* __restrict__ s, int sbs,
    int blk,
    int*   __restrict__ idxOut,
    float* __restrict__ d2Out,
    float* sxs, float* sys, float* szs, float* smd, int* smi)
{
    int b  = blk >> 3;
    int n0 = (blk & 7) * 64;
    const float* sb = s + b * sbs;
    for (int i = threadIdx.x; i < NPTS; i += 128) {
        sxs[i] = sb[i*3 + 0];
        sys[i] = sb[i*3 + 1];
        szs[i] = sb[i*3 + 2];
    }
    __syncthreads();

    int qi   = threadIdx.x & 63;
    int half = threadIdx.x >> 6;
    int n = n0 + qi;
    const float* qp = q + b * qbs + n * 3;
    float qx = qp[0], qy = qp[1], qz = qp[2];

    float bd[KNN]; int bi[KNN];
    #pragma unroll
    for (int k = 0; k < KNN; k++) { bd[k] = 3.4e38f; bi[k] = 0; }

    int j0 = half * 256;
    for (int j = j0; j < j0 + 256; j++) {
        float dx = __fadd_rn(qx, -sxs[j]);
        float dy = __fadd_rn(qy, -sys[j]);
        float dz = __fadd_rn(qz, -szs[j]);
        float d = __fadd_rn(__fadd_rn(__fmul_rn(dx, dx), __fmul_rn(dy, dy)),
                            __fmul_rn(dz, dz));
        if (d < bd[KNN-1]) {
            bd[KNN-1] = d; bi[KNN-1] = j;
            #pragma unroll
            for (int t = KNN-1; t > 0; --t) {
                if (bd[t] < bd[t-1]) {
                    float td = bd[t]; bd[t] = bd[t-1]; bd[t-1] = td;
                    int   ti = bi[t]; bi[t] = bi[t-1]; bi[t-1] = ti;
                }
            }
        }
    }
    #pragma unroll
    for (int k = 0; k < KNN; k++) {
        smd[(half * 64 + qi) * KNN + k] = bd[k];
        smi[(half * 64 + qi) * KNN + k] = bi[k];
    }
    __syncthreads();

    if (threadIdx.x < 64) {
        const float* da = &smd[qi * KNN];
        const int*   ia = &smi[qi * KNN];
        const float* db = &smd[(64 + qi) * KNN];
        const int*   ib = &smi[(64 + qi) * KNN];
        int pa = 0, pb = 0;
        size_t base = (size_t)(b * NPTS + n) * KNN;
        #pragma unroll
        for (int k = 0; k < KNN; k++) {
            float va = da[pa], vb = db[pb];
            bool takeA = (va <= vb);
            idxOut[base + k] = takeA ? ia[pa] : ib[pb];
            d2Out [base + k] = takeA ? va : vb;
            pa += takeA ? 1 : 0;
            pb += takeA ? 0 : 1;
        }
    }
}

__global__ __launch_bounds__(128) void topk_kernel(
    const float* __restrict__ q, int qbs,
    const float* __restrict__ s, int sbs,
    int*   __restrict__ idxOut,
    float* __restrict__ d2Out)
{
    __shared__ float sxs[NPTS], sys[NPTS], szs[NPTS];
    __shared__ float smd[2 * 64 * KNN];
    __shared__ int   smi[2 * 64 * KNN];
    topk_body(q, qbs, s, sbs, blockIdx.x, idxOut, d2Out,
              sxs, sys, szs, smd, smi);
}

__global__ __launch_bounds__(128) void topk_pre_kernel(
    const float* __restrict__ frames)
{
    __shared__ float sxs[NPTS], sys[NPTS], szs[NPTS];
    __shared__ float smd[2 * 64 * KNN];
    __shared__ int   smi[2 * 64 * KNN];

    const int FBS = SEQ * NPTS * 3;
    const int FRM = NPTS * 3;
    int t = blockIdx.y;
    int qf = (t < 6) ? t : 5;
    int sf = (t == 0) ? 0 : ((t < 6) ? (t - 1) : 5);
    topk_body(frames + qf * FRM, FBS, frames + sf * FRM, FBS, blockIdx.x,
              g_idx + (size_t)t * BNT * KNN, g_d2 + (size_t)t * BNT * KNN,
              sxs, sys, szs, smd, smi);
}

// ---------------------------------------------------------------------------
// FUSED combine1+combine2 (validated round 13)
// ---------------------------------------------------------------------------
__global__ __launch_bounds__(256) void combine12_kernel(
    const float* __restrict__ Z1,
    const float* __restrict__ Z2,
    const float* __restrict__ W1,
    const float* __restrict__ b1,
    const float* __restrict__ W2,
    const float* __restrict__ b2,
    const int*   __restrict__ idx,
    const float* __restrict__ d2,
    const float* __restrict__ qx, int qbs,
    float r2c1, float r2c2,
    bf16* __restrict__ f1oh, bf16* __restrict__ f1ol,
    bf16* __restrict__ f2oh, bf16* __restrict__ f2ol,
    const float* __restrict__ Wf2)
{
    __shared__ int    sRow1[8][KNN], sRow2[8][KNN];
    __shared__ float2 frow2[8][64];
    __shared__ float2 wn2[64][64];
    __shared__ float  sQ2[8][128];

    int tid = threadIdx.x;
    int p0 = blockIdx.x * 8;

    if (tid < 64) {
        int pt = tid >> 3, k = tid & 7;
        int p = p0 + pt;
        int b = p >> 9;
        int raw = idx[p * KNN + k];
        int i0  = idx[p * KNN];
        float dd = d2[p * KNN + k];
        sRow1[pt][k] = b * NPTS + ((dd <= r2c1) ? raw : i0);
        sRow2[pt][k] = b * NPTS + ((dd <= r2c2) ? raw : i0);
    }
    #pragma unroll 4
    for (int i = tid; i < 64 * 64; i += 256)
        reinterpret_cast<float2*>(wn2)[i] =
            reinterpret_cast<const float2*>(Wf2)[i];
    __syncthreads();

    int x = tid & 31, y = tid >> 5;
    {
        int p = p0 + y;
        int b = p >> 9, n = p & 511;
        int j0 = 2 * x;
        float2 w0 = *reinterpret_cast<const float2*>(&W1[j0]);
        float2 w1 = *reinterpret_cast<const float2*>(&W1[64 + j0]);
        float2 w2 = *reinterpret_cast<const float2*>(&W1[128 + j0]);
        float2 bb = *reinterpret_cast<const float2*>(&b1[j0]);

        const float* qp = qx + b * qbs + n * 3;
        float q0 = qp[0], q1 = qp[1], q2v = qp[2];
        float tx = q0 * w0.x + q1 * w1.x + q2v * w2.x;
        float ty = q0 * w0.y + q1 * w1.y + q2v * w2.y;

        float mx = -3.4e38f, my = -3.4e38f;
        #pragma unroll
        for (int k = 0; k < KNN; k++) {
            int row = sRow1[y][k];
            float2 zf = unpk(__ldg(reinterpret_cast<const ull*>(&Z1[(size_t)row * 64 + j0])));
            mx = fmaxf(mx, zf.x);
            my = fmaxf(my, zf.y);
        }
        float ox = bb.x + (mx - tx);
        float oy = bb.y + (my - ty);

        pack_store(f1oh, f1ol, (size_t)p * 64 + j0, ox, oy);

        frow2[y][j0]     = make_float2(ox, ox);
        frow2[y][j0 + 1] = make_float2(oy, oy);
    }
    __syncthreads();

    {
        ull a0 = 0ull, a1 = 0ull;
        #pragma unroll 8
        for (int c = 0; c < 64; c++) {
            ull f = *reinterpret_cast<const ull*>(&frow2[y][c]);
            ffma2(a0, f, *reinterpret_cast<const ull*>(&wn2[c][x]));
            ffma2(a1, f, *reinterpret_cast<const ull*>(&wn2[c][x + 32]));
        }
        float2 qo0 = unpk(a0), qo1 = unpk(a1);
        int j0 = 2 * x;
        sQ2[y][j0]          = qo0.x;
        sQ2[y][j0 + 1]      = qo0.y;
        sQ2[y][64 + j0]     = qo1.x;
        sQ2[y][64 + j0 + 1] = qo1.y;
    }
    __syncthreads();

    {
        int x2 = tid & 63, yg = tid >> 6;
        int j0 = 2 * x2;
        float2 w0 = *reinterpret_cast<const float2*>(&W2[j0]);
        float2 w1 = *reinterpret_cast<const float2*>(&W2[128 + j0]);
        float2 w2 = *reinterpret_cast<const float2*>(&W2[256 + j0]);
        float2 bb = *reinterpret_cast<const float2*>(&b2[j0]);

        #pragma unroll
        for (int pt = yg; pt < 8; pt += 4) {
            int p = p0 + pt;
            int b = p >> 9, n = p & 511;
            const float* qp = qx + b * qbs + n * 3;
            float q0 = qp[0], q1 = qp[1], q2v = qp[2];
            float tx = q0 * w0.x + q1 * w1.x + q2v * w2.x;
            float ty = q0 * w0.y + q1 * w1.y + q2v * w2.y;

            float mx = -3.4e38f, my = -3.4e38f;
            #pragma unroll
            for (int k = 0; k < KNN; k++) {
                int row = sRow2[pt][k];
                float2 zf = unpk(__ldg(reinterpret_cast<const ull*>(&Z2[(size_t)row * 128 + j0])));
                mx = fmaxf(mx, zf.x);
                my = fmaxf(my, zf.y);
            }
            float2 qv = *reinterpret_cast<const float2*>(&sQ2[pt][j0]);
            float ox = bb.x + qv.x + (mx - tx);
            float oy = bb.y + qv.y + (my - ty);
            pack_store(f2oh, f2ol, (size_t)p * 128 + j0, ox, oy);
        }
    }
}

// ---------------------------------------------------------------------------
// static stream/event setup
// ---------------------------------------------------------------------------
struct SideStream {
    cudaStream_t sB = nullptr;
    cudaEvent_t  evZ12 = nullptr, evZ3 = nullptr, evC12 = nullptr, evC3 = nullptr;
    bool ok = false;
    SideStream() {
        if (cudaStreamCreateWithFlags(&sB, cudaStreamNonBlocking) != cudaSuccess) return;
        cudaEventCreateWithFlags(&evZ12, cudaEventDisableTiming);
        cudaEventCreateWithFlags(&evZ3,  cudaEventDisableTiming);
        cudaEventCreateWithFlags(&evC12, cudaEventDisableTiming);
        cudaEventCreateWithFlags(&evC3,  cudaEventDisableTiming);
        noop_kernel<<<1, 1, 0, sB>>>();
        cudaEventRecord(evZ12, sB);
        cudaEventRecord(evZ3, sB);
        cudaEventRecord(evC12, sB);
        cudaEventRecord(evC3, sB);
        cudaStreamSynchronize(sB);
        ok = true;
    }
};
static SideStream g_ss;

// ---------------------------------------------------------------------------
// host orchestration
// ---------------------------------------------------------------------------
extern "C" void kernel_launch(void* const* d_in, const int* in_sizes, int n_in,
                              void* d_out, int out_size)
{
    (void)in_sizes; (void)n_in; (void)out_size;

    const float* frames = (const float*)d_in[0];
    const float* W1 = (const float*)d_in[1];
    const float* b1 = (const float*)d_in[2];
    const float* W2 = (const float*)d_in[3];
    const float* b2 = (const float*)d_in[4];
    const float* W3 = (const float*)d_in[5];
    const float* b3 = (const float*)d_in[6];
    const float* Wm = (const float*)d_in[7];
    const float* bm = (const float*)d_in[8];
    const float* Wl = (const float*)d_in[9];
    const float* bl = (const float*)d_in[10];
    float* out = (float*)d_out;

    bf16 *f1h, *f1l, *f2h, *f2l, *f3h, *f3l;
    float *Z1, *Z2, *Z3;
    int* idxp; float* d2p;
    bf16 *wmh, *wml;
    { void* t;
      cudaGetSymbolAddress(&t, g_f1h); f1h = (bf16*)t;
      cudaGetSymbolAddress(&t, g_f1l); f1l = (bf16*)t;
      cudaGetSymbolAddress(&t, g_f2h); f2h = (bf16*)t;
      cudaGetSymbolAddress(&t, g_f2l); f2l = (bf16*)t;
      cudaGetSymbolAddress(&t, g_f3h); f3h = (bf16*)t;
      cudaGetSymbolAddress(&t, g_f3l); f3l = (bf16*)t;
      cudaGetSymbolAddress(&t, g_Z1); Z1 = (float*)t;
      cudaGetSymbolAddress(&t, g_Z2); Z2 = (float*)t;
      cudaGetSymbolAddress(&t, g_Z3); Z3 = (float*)t;
      cudaGetSymbolAddress(&t, g_idx); idxp = (int*)t;
      cudaGetSymbolAddress(&t, g_d2);  d2p  = (float*)t;
      cudaGetSymbolAddress(&t, g_Wmh);  wmh  = (bf16*)t;
      cudaGetSymbolAddress(&t, g_Wml);  wml  = (bf16*)t;
    }

    cudaFuncSetAttribute(z12_kernel,
        cudaFuncAttributeMaxDynamicSharedMemorySize, DSMEM);
    cudaFuncSetAttribute(z3_kernel,
        cudaFuncAttributeMaxDynamicSharedMemorySize, DSMEM);
    cudaFuncSetAttribute(q3c3_kernel,
        cudaFuncAttributeMaxDynamicSharedMemorySize, DSMEM);
    cudaFuncSetAttribute(hmma_mlp_kernel,
        cudaFuncAttributeMaxDynamicSharedMemorySize, DSMEM);

    const int FBS = SEQ * NPTS * 3;
    const int OBS = HALF * NPTS * 3;
    const int FRM = NPTS * 3;

    const double R0 = 4.0 + 1e-6, R1 = 8.0 + 1e-6, R2 = 12.0 + 1e-6;
    const float r2c1 = (float)(R0 * R0);
    const float r2c2 = (float)(R1 * R1);
    const float r2c3 = (float)(R2 * R2);

    const float* Wn1 = W1 + 3 * 64;
    const float* Wf2 = W2 + 3 * 128;
    const float* Wn2 = W2 + (3 + 64) * 128;
    const float* Wf3 = W3 + 3 * 256;
    const float* Wn3 = W3 + (3 + 128) * 256;

    init_kernel<<<512, 256>>>(Wn1, Wn2, Wn3, Wf3, Wm);
    topk_pre_kernel<<<dim3(128, 7), 128, 0, g_ss.sB>>>(frames);
    cudaEventRecord(g_ss.evC12, 0);
    cudaEventRecord(g_ss.evC3, 0);

    for (int t = 0; t < SEQ; t++) {
        const float *q, *s; int qbs, sbs;
        if (t < HALF) {
            q = frames + t * FRM;                       qbs = FBS;
            s = frames + (t ? (t - 1) : 0) * FRM;       sbs = FBS;
        } else if (t == HALF) {
            q = frames + (HALF - 1) * FRM;              qbs = FBS;
            s = q;                                      sbs = FBS;
        } else if (t == HALF + 1) {
            q = out;                                    qbs = OBS;
            s = frames + (HALF - 1) * FRM;              sbs = FBS;
        } else {
            q = out + (t - HALF - 1) * FRM;             qbs = OBS;
            s = out + (t - HALF - 2) * FRM;             sbs = OBS;
        }

        int pin = t & 1, pout = 1 - pin;
        bf16* f1ih = f1h + pin  * BNT * 64;
        bf16* f1il = f1l + pin  * BNT * 64;
        bf16* f1oh = f1h + pout * BNT * 64;
        bf16* f1ol = f1l + pout * BNT * 64;
        bf16* f2ih = f2h + pin  * BNT * 128;
        bf16* f2il = f2l + pin  * BNT * 128;
        bf16* f2oh = f2h + pout * BNT * 128;
        bf16* f2ol = f2l + pout * BNT * 128;
        bf16* f3ih = f3h + pin  * BNT * 256;
        bf16* f3il = f3l + pin  * BNT * 256;
        bf16* f3oh = f3h + pout * BNT * 256;
        bf16* f3ol = f3l + pout * BNT * 256;

        float* z1 = Z1 + (size_t)(t & 1) * BNT * 64;
        float* z2 = Z2 + (size_t)(t & 1) * BNT * 128;
        float* z3 = Z3 + (size_t)(t & 1) * BNT * 256;

        int slot = (t < 7) ? t : 7;
        int*   idxs = idxp + (size_t)slot * BNT * KNN;
        float* d2s  = d2p  + (size_t)slot * BNT * KNN;

        // ---- side stream: z12 gated on c12(t-1); z3 gated on c3(t-1) ----
        cudaStreamWaitEvent(g_ss.sB, g_ss.evC12, 0);
        z12_kernel<<<dim3(64, 3), 128, DSMEM, g_ss.sB>>>(
            f1ih, f1il, f2ih, f2il, W1, W2, s, sbs, z1, z2);
        cudaEventRecord(g_ss.evZ12, g_ss.sB);
        cudaStreamWaitEvent(g_ss.sB, g_ss.evC3, 0);
        z3_kernel<<<dim3(64, 4), 128, DSMEM, g_ss.sB>>>(
            f3ih, f3il, W3, s, sbs, z3);
        cudaEventRecord(g_ss.evZ3, g_ss.sB);

        // ---- main stream ----
        if (t >= 7)
            topk_kernel<<<128, 128>>>(q, qbs, s, sbs, idxs, d2s);

        cudaStreamWaitEvent(0, g_ss.evZ12, 0);

        combine12_kernel<<<BNT / 8, 256>>>(
            z1, z2, W1, b1, W2, b2, idxs, d2s, q, qbs, r2c1, r2c2,
            f1oh, f1ol, f2oh, f2ol, Wf2);
        cudaEventRecord(g_ss.evC12, 0);

        cudaStreamWaitEvent(0, g_ss.evZ3, 0);

        // Q3 GEMM + fused combine3 -> f3o
        q3c3_kernel<<<dim3(64, 4), 128, DSMEM>>>(
            f2oh, f2ol, z3, W3, b3, idxs, d2s, q, qbs, r2c3,
            f3oh, f3ol);
        cudaEventRecord(g_ss.evC3, 0);

        if (t >= HALF) {
            hmma_mlp_kernel<<<64, 128, DSMEM>>>(
                f3oh, f3ol, wmh, wml, 256,
                bm, Wl, bl, q, qbs, out + (t - HALF) * FRM, OBS);
        }
    }
}

// round 15
// speedup vs baseline: 1.1620x; 1.1620x over previous
#include <cuda_runtime.h>
#include <cuda_bf16.h>
#include <cstdint>

typedef unsigned long long ull;
typedef __nv_bfloat16 bf16;

#define NB    16
#define NPTS  512
#define BNT   (NB*NPTS)   // 8192
#define KNN   8
#define SEQ   12
#define HALF  6

// ---------------------------------------------------------------------------
// Scratch (static device globals).  Z buffers double-buffered by step parity.
// ---------------------------------------------------------------------------
__device__ __align__(16) bf16 g_f1h[2 * BNT * 64],  g_f1l[2 * BNT * 64];
__device__ __align__(16) bf16 g_f2h[2 * BNT * 128], g_f2l[2 * BNT * 128];
__device__ __align__(16) bf16 g_f3h[2 * BNT * 256], g_f3l[2 * BNT * 256];
__device__ __align__(16) float g_Z1[2 * BNT * 64];
__device__ __align__(16) float g_Z2[2 * BNT * 128];
__device__ __align__(16) float g_Z3[2 * BNT * 256];
__device__ __align__(16) float g_Q3[BNT * 256];
// 8 slots: 0..6 = precomputed warmup topk, 7 = dynamic (steps 7..11)
__device__ __align__(16) int   g_idx[8 * BNT * KNN];
__device__ __align__(16) float g_d2 [8 * BNT * KNN];
__device__ __align__(16) bf16 g_Wn1h[64*64],   g_Wn1l[64*64];
__device__ __align__(16) bf16 g_Wn2h[128*128], g_Wn2l[128*128];
__device__ __align__(16) bf16 g_Wn3h[256*256], g_Wn3l[256*256];
__device__ __align__(16) bf16 g_Wf3h[128*256], g_Wf3l[128*256];
__device__ __align__(16) bf16 g_Wmh [256*64],  g_Wml [256*64];

// ---------------------------------------------------------------------------
// helpers
// ---------------------------------------------------------------------------
__device__ __forceinline__ void ffma2(ull& d, ull a, ull b)
{
    asm("fma.rn.f32x2 %0, %1, %2, %0;" : "+l"(d) : "l"(a), "l"(b));
}
__device__ __forceinline__ float2 unpk(ull v)
{
    float2 f;
    asm("mov.b64 {%0, %1}, %2;" : "=f"(f.x), "=f"(f.y) : "l"(v));
    return f;
}
__device__ __forceinline__ uint32_t smem_u32(const void* p)
{
    uint32_t a;
    asm("{ .reg .u64 t; cvta.to.shared.u64 t, %1; cvt.u32.u64 %0, t; }"
        : "=r"(a) : "l"(p));
    return a;
}
__device__ __forceinline__ void ldsm4(uint32_t* r, uint32_t a)
{
    asm volatile("ldmatrix.sync.aligned.m8n8.x4.shared.b16 {%0,%1,%2,%3}, [%4];"
        : "=r"(r[0]), "=r"(r[1]), "=r"(r[2]), "=r"(r[3]) : "r"(a));
}
__device__ __forceinline__ void ldsm4t(uint32_t* r, uint32_t a)
{
    asm volatile("ldmatrix.sync.aligned.m8n8.x4.trans.shared.b16 {%0,%1,%2,%3}, [%4];"
        : "=r"(r[0]), "=r"(r[1]), "=r"(r[2]), "=r"(r[3]) : "r"(a));
}
__device__ __forceinline__ void mma16816(float* d, const uint32_t* a,
                                         uint32_t b0, uint32_t b1)
{
    asm volatile(
        "mma.sync.aligned.m16n8k16.row.col.f32.bf16.bf16.f32 "
        "{%0,%1,%2,%3}, {%4,%5,%6,%7}, {%8,%9}, {%0,%1,%2,%3};"
        : "+f"(d[0]), "+f"(d[1]), "+f"(d[2]), "+f"(d[3])
        : "r"(a[0]), "r"(a[1]), "r"(a[2]), "r"(a[3]), "r"(b0), "r"(b1));
}
__device__ __forceinline__ void cp16(uint32_t dst, const void* src)
{
    asm volatile("cp.async.cg.shared.global [%0], [%1], 16;"
                 :: "r"(dst), "l"(src));
}
__device__ __forceinline__ void cp_commit()
{
    asm volatile("cp.async.commit_group;");
}
template<int N>
__device__ __forceinline__ void cp_wait()
{
    asm volatile("cp.async.wait_group %0;" :: "n"(N));
}
__device__ __forceinline__ void pack_store(bf16* H, bf16* L, size_t off,
                                           float ox, float oy)
{
    bf16 hx = __float2bfloat16_rn(ox);
    bf16 hy = __float2bfloat16_rn(oy);
    bf16 lx = __float2bfloat16_rn(ox - __bfloat162float(hx));
    bf16 ly = __float2bfloat16_rn(oy - __bfloat162float(hy));
    uint32_t ph = (uint32_t)*reinterpret_cast<uint16_t*>(&hx)
                | ((uint32_t)*reinterpret_cast<uint16_t*>(&hy) << 16);
    uint32_t pl = (uint32_t)*reinterpret_cast<uint16_t*>(&lx)
                | ((uint32_t)*reinterpret_cast<uint16_t*>(&ly) << 16);
    *reinterpret_cast<uint32_t*>(H + off) = ph;
    *reinterpret_cast<uint32_t*>(L + off) = pl;
}

// ---------------------------------------------------------------------------
// init: zero states + weight hi/lo splits
// ---------------------------------------------------------------------------
__device__ __forceinline__ void wsplit(const float* W, bf16* hi, bf16* lo,
                                       int total, int i0, int stride)
{
    for (int i = i0; i < total; i += stride) {
        float x = W[i];
        bf16 h = __float2bfloat16_rn(x);
        bf16 l = __float2bfloat16_rn(x - __bfloat162float(h));
        hi[i] = h;
        lo[i] = l;
    }
}

__global__ void init_kernel(const float* __restrict__ Wn1,
                            const float* __restrict__ Wn2,
                            const float* __restrict__ Wn3,
                            const float* __restrict__ Wf3,
                            const float* __restrict__ Wm)
{
    int stride = gridDim.x * blockDim.x;
    int i0 = blockIdx.x * blockDim.x + threadIdx.x;
    uint32_t* a;
    a = reinterpret_cast<uint32_t*>(g_f1h);
    for (int i = i0; i < BNT * 64;  i += stride) a[i] = 0u;
    a = reinterpret_cast<uint32_t*>(g_f1l);
    for (int i = i0; i < BNT * 64;  i += stride) a[i] = 0u;
    a = reinterpret_cast<uint32_t*>(g_f2h);
    for (int i = i0; i < BNT * 128; i += stride) a[i] = 0u;
    a = reinterpret_cast<uint32_t*>(g_f2l);
    for (int i = i0; i < BNT * 128; i += stride) a[i] = 0u;
    a = reinterpret_cast<uint32_t*>(g_f3h);
    for (int i = i0; i < BNT * 256; i += stride) a[i] = 0u;
    a = reinterpret_cast<uint32_t*>(g_f3l);
    for (int i = i0; i < BNT * 256; i += stride) a[i] = 0u;

    wsplit(Wn1, g_Wn1h, g_Wn1l, 64*64,   i0, stride);
    wsplit(Wn2, g_Wn2h, g_Wn2l, 128*128, i0, stride);
    wsplit(Wn3, g_Wn3h, g_Wn3l, 256*256, i0, stride);
    wsplit(Wf3, g_Wf3h, g_Wf3l, 128*256, i0, stride);
    wsplit(Wm,  g_Wmh,  g_Wml,  256*64,  i0, stride);
}

__global__ void noop_kernel() {}

// ---------------------------------------------------------------------------
// 128x64 HMMA tile, 4 warps, warp tile 32m x 64n, split-bf16, BK=32,
// double-buffered cp.async. (validated round 10)
// MODE 0: plain fp32 store. MODE 1: +s.Wd epilogue (Z). MODE 2: fused MLP.
// ---------------------------------------------------------------------------
#define BUFSZ   29696
#define DSMEM   (2 * BUFSZ)     // 59392

template<int MODE>
__device__ __forceinline__ void gemm_tile(
    char* sm, int tid,
    const bf16* __restrict__ Ah, const bf16* __restrict__ Al,
    const bf16* __restrict__ Bh, const bf16* __restrict__ Bl,
    float* __restrict__ C, int N, int K, int rowBase, int nStrip,
    const float* sxyz, int sbs, const float* Wfull,
    const float* bm, const float* Wl, const float* bl,
    const float* cur, int cbs, float* dst, int dbs)
{
    int warp = tid >> 5, lane = tid & 31;

    float acc[2][8][4];
    #pragma unroll
    for (int mg = 0; mg < 2; mg++)
        #pragma unroll
        for (int i = 0; i < 8; i++)
            #pragma unroll
            for (int j = 0; j < 4; j++) acc[mg][i][j] = 0.f;

    uint32_t smBase = smem_u32(sm);

    auto stage = [&](int buf, int k0) {
        uint32_t base = smBase + buf * BUFSZ;
        #pragma unroll
        for (int i = 0; i < 4; i++) {
            int c = tid + i * 128;
            int row = c >> 2, col8 = (c & 3) * 8;
            uint32_t d = base + row * 80 + col8 * 2;
            const bf16* sh = Ah + (size_t)(rowBase + row) * K + k0 + col8;
            const bf16* sl = Al + (size_t)(rowBase + row) * K + k0 + col8;
            cp16(d,         sh);
            cp16(d + 10240, sl);
        }
        #pragma unroll
        for (int i = 0; i < 2; i++) {
            int c = tid + i * 128;
            int row = c >> 3, col8 = (c & 7) * 8;
            uint32_t d = base + 20480 + row * 144 + col8 * 2;
            const bf16* sh = Bh + (size_t)(k0 + row) * N + nStrip + col8;
            const bf16* sl = Bl + (size_t)(k0 + row) * N + nStrip + col8;
            cp16(d,        sh);
            cp16(d + 4608, sl);
        }
        cp_commit();
    };

    int nT = K >> 5;
    stage(0, 0);

    int aLane = lane & 15;
    int hi8   = (lane >> 4) * 8;
    int bRow  = lane & 15;

    for (int it = 0; it < nT; it++) {
        int buf = it & 1;
        if (it + 1 < nT) { stage(buf ^ 1, (it + 1) * 32); cp_wait<1>(); }
        else             { cp_wait<0>(); }
        __syncthreads();

        uint32_t base = smBase + buf * BUFSZ;
        #pragma unroll
        for (int kk = 0; kk < 32; kk += 16) {
            uint32_t ah[2][4], al[2][4];
            #pragma unroll
            for (int mg = 0; mg < 2; mg++) {
                int row = warp * 32 + mg * 16 + aLane;
                uint32_t ad = base + row * 80 + (kk + hi8) * 2;
                ldsm4(ah[mg], ad);
                ldsm4(al[mg], ad + 10240);
            }
            #pragma unroll
            for (int np = 0; np < 4; np++) {
                uint32_t bd = base + 20480 + (kk + bRow) * 144 + (np * 16 + hi8) * 2;
                uint32_t bh[4], bl2[4];
                ldsm4t(bh,  bd);
                ldsm4t(bl2, bd + 4608);
                #pragma unroll
                for (int mg = 0; mg < 2; mg++) {
                    mma16816(acc[mg][np*2],     ah[mg], bh[0], bh[1]);
                    mma16816(acc[mg][np*2],     ah[mg], bl2[0], bl2[1]);
                    mma16816(acc[mg][np*2],     al[mg], bh[0], bh[1]);
                    mma16816(acc[mg][np*2 + 1], ah[mg], bh[2], bh[3]);
                    mma16816(acc[mg][np*2 + 1], ah[mg], bl2[2], bl2[3]);
                    mma16816(acc[mg][np*2 + 1], al[mg], bh[2], bh[3]);
                }
            }
        }
        __syncthreads();
    }

    int g = lane >> 2, tg = lane & 3;
    if constexpr (MODE == 0) {
        #pragma unroll
        for (int mg = 0; mg < 2; mg++) {
            float* Crow = C + (size_t)(rowBase + warp * 32 + mg * 16 + g) * N
                        + nStrip + tg * 2;
            #pragma unroll
            for (int ng = 0; ng < 8; ng++) {
                *reinterpret_cast<float2*>(Crow + ng * 8) =
                    make_float2(acc[mg][ng][0], acc[mg][ng][1]);
                *reinterpret_cast<float2*>(Crow + (size_t)8 * N + ng * 8) =
                    make_float2(acc[mg][ng][2], acc[mg][ng][3]);
            }
        }
    } else if constexpr (MODE == 1) {
        #pragma unroll
        for (int mg = 0; mg < 2; mg++) {
            int p0_ = rowBase + warp * 32 + mg * 16 + g;
            int p1_ = p0_ + 8;
            int b0 = p0_ >> 9, n0 = p0_ & 511, n1 = p1_ & 511;
            const float* sp0 = sxyz + b0 * sbs + n0 * 3;
            const float* sp1 = sxyz + b0 * sbs + n1 * 3;
            float s00 = sp0[0], s01 = sp0[1], s02 = sp0[2];
            float s10 = sp1[0], s11 = sp1[1], s12 = sp1[2];
            float* Crow = C + (size_t)p0_ * N + nStrip + tg * 2;
            #pragma unroll
            for (int ng = 0; ng < 8; ng++) {
                int col = nStrip + ng * 8 + tg * 2;
                float w00 = __ldg(Wfull + col),         w01 = __ldg(Wfull + col + 1);
                float w10 = __ldg(Wfull + N + col),     w11 = __ldg(Wfull + N + col + 1);
                float w20 = __ldg(Wfull + 2 * N + col), w21 = __ldg(Wfull + 2 * N + col + 1);
                float a0 = s00 * w00 + s01 * w10 + s02 * w20;
                float a1 = s00 * w01 + s01 * w11 + s02 * w21;
                float c0 = s10 * w00 + s11 * w10 + s12 * w20;
                float c1 = s10 * w01 + s11 * w11 + s12 * w21;
                *reinterpret_cast<float2*>(Crow + ng * 8) =
                    make_float2(acc[mg][ng][0] + a0, acc[mg][ng][1] + a1);
                *reinterpret_cast<float2*>(Crow + (size_t)8 * N + ng * 8) =
                    make_float2(acc[mg][ng][2] + c0, acc[mg][ng][3] + c1);
            }
        }
    } else {
        #pragma unroll
        for (int mg = 0; mg < 2; mg++) {
            float m0[3] = {0, 0, 0}, m1[3] = {0, 0, 0};
            #pragma unroll
            for (int ng = 0; ng < 8; ng++) {
                int j0 = ng * 8 + tg * 2;
                float h00 = fmaxf(acc[mg][ng][0] + __ldg(bm + j0),     0.f);
                float h01 = fmaxf(acc[mg][ng][1] + __ldg(bm + j0 + 1), 0.f);
                float h10 = fmaxf(acc[mg][ng][2] + __ldg(bm + j0),     0.f);
                float h11 = fmaxf(acc[mg][ng][3] + __ldg(bm + j0 + 1), 0.f);
                #pragma unroll
                for (int d = 0; d < 3; d++) {
                    float w0 = __ldg(Wl + j0 * 3 + d);
                    float w1 = __ldg(Wl + (j0 + 1) * 3 + d);
                    m0[d] += h00 * w0 + h01 * w1;
                    m1[d] += h10 * w0 + h11 * w1;
                }
            }
            #pragma unroll
            for (int d = 0; d < 3; d++) {
                m0[d] += __shfl_xor_sync(0xFFFFFFFFu, m0[d], 1);
                m0[d] += __shfl_xor_sync(0xFFFFFFFFu, m0[d], 2);
                m1[d] += __shfl_xor_sync(0xFFFFFFFFu, m1[d], 1);
                m1[d] += __shfl_xor_sync(0xFFFFFFFFu, m1[d], 2);
            }
            if (tg == 0) {
                int p0_ = rowBase + warp * 32 + mg * 16 + g;
                #pragma unroll
                for (int r = 0; r < 2; r++) {
                    int p_ = p0_ + r * 8;
                    int b = p_ >> 9, n = p_ & 511;
                    const float* cp = cur + b * cbs + n * 3;
                    float*       dp = dst + b * dbs + n * 3;
                    float* mm = r ? m1 : m0;
                    #pragma unroll
                    for (int d = 0; d < 3; d++)
                        dp[d] = cp[d] + __ldg(bl + d) + mm[d];
                }
            }
        }
    }
}

// ---------------------------------------------------------------------------
// Z GEMM kernels (side stream): Z = f_in @ Wn + s.Wd  (parity pointer passed)
// ---------------------------------------------------------------------------
__global__ __launch_bounds__(128) void z12_kernel(
    const bf16* f1h, const bf16* f1l, const bf16* f2h, const bf16* f2l,
    const float* __restrict__ W1, const float* __restrict__ W2,
    const float* __restrict__ s, int sbs,
    float* __restrict__ Z1, float* __restrict__ Z2)
{
    extern __shared__ __align__(16) char sm[];
    if (blockIdx.y == 0) {
        gemm_tile<1>(sm, threadIdx.x, f1h, f1l, g_Wn1h, g_Wn1l, Z1,
                     64, 64, blockIdx.x * 128, 0,
                     s, sbs, W1, nullptr, nullptr, nullptr,
                     nullptr, 0, nullptr, 0);
    } else {
        gemm_tile<1>(sm, threadIdx.x, f2h, f2l, g_Wn2h, g_Wn2l, Z2,
                     128, 128, blockIdx.x * 128, (blockIdx.y - 1) * 64,
                     s, sbs, W2, nullptr, nullptr, nullptr,
                     nullptr, 0, nullptr, 0);
    }
}

__global__ __launch_bounds__(128) void z3_kernel(
    const bf16* f3h, const bf16* f3l,
    const float* __restrict__ W3,
    const float* __restrict__ s, int sbs,
    float* __restrict__ Z3)
{
    extern __shared__ __align__(16) char sm[];
    gemm_tile<1>(sm, threadIdx.x, f3h, f3l, g_Wn3h, g_Wn3l, Z3,
                 256, 256, blockIdx.x * 128, blockIdx.y * 64,
                 s, sbs, W3, nullptr, nullptr, nullptr,
                 nullptr, 0, nullptr, 0);
}

__global__ __launch_bounds__(128) void hmma_kernel(
    const bf16* Ah, const bf16* Al, const bf16* Bh, const bf16* Bl,
    float* C, int N, int K)
{
    extern __shared__ __align__(16) char sm[];
    gemm_tile<0>(sm, threadIdx.x, Ah, Al, Bh, Bl, C, N, K,
                 blockIdx.x * 128, blockIdx.y * 64,
                 nullptr, 0, nullptr, nullptr, nullptr, nullptr,
                 nullptr, 0, nullptr, 0);
}

__global__ __launch_bounds__(128) void hmma_mlp_kernel(
    const bf16* Ah, const bf16* Al, const bf16* Bh, const bf16* Bl, int K,
    const float* bm, const float* Wl, const float* bl,
    const float* cur, int cbs, float* dst, int dbs)
{
    extern __shared__ __align__(16) char sm[];
    gemm_tile<2>(sm, threadIdx.x, Ah, Al, Bh, Bl, nullptr, 64, K,
                 blockIdx.x * 128, 0,
                 nullptr, 0, nullptr, bm, Wl, bl, cur, cbs, dst, dbs);
}

// ---------------------------------------------------------------------------
// top-8 body: 256 threads per block, 4-way split (128 sources each) + merge
// (4-way merge mechanism validated in round-8 mega kernel)
// ---------------------------------------------------------------------------
__device__ __forceinline__ void topk_body4(
    const float* __restrict__ q, int qbs,
    const float* __restrict__ s, int sbs,
    int blk,
    int*   __restrict__ idxOut,
    float* __restrict__ d2Out,
    float* sxs, float* sys, float* szs, float* smd, int* smi)
{
    int b  = blk >> 3;
    int n0 = (blk & 7) * 64;
    const float* sb = s + b * sbs;
    for (int i = threadIdx.x; i < NPTS; i += 256) {
        sxs[i] = sb[i*3 + 0];
        sys[i] = sb[i*3 + 1];
        szs[i] = sb[i*3 + 2];
    }
    __syncthreads();

    int qi      = threadIdx.x & 63;
    int quarter = threadIdx.x >> 6;
    int n = n0 + qi;
    const float* qp = q + b * qbs + n * 3;
    float qx = qp[0], qy = qp[1], qz = qp[2];

    float bd[KNN]; int bi[KNN];
    #pragma unroll
    for (int k = 0; k < KNN; k++) { bd[k] = 3.4e38f; bi[k] = 0; }

    int j0 = quarter * 128;
    for (int j = j0; j < j0 + 128; j++) {
        float dx = __fadd_rn(qx, -sxs[j]);
        float dy = __fadd_rn(qy, -sys[j]);
        float dz = __fadd_rn(qz, -szs[j]);
        float d = __fadd_rn(__fadd_rn(__fmul_rn(dx, dx), __fmul_rn(dy, dy)),
                            __fmul_rn(dz, dz));
        if (d < bd[KNN-1]) {
            bd[KNN-1] = d; bi[KNN-1] = j;
            #pragma unroll
            for (int t = KNN-1; t > 0; --t) {
                if (bd[t] < bd[t-1]) {
                    float td = bd[t]; bd[t] = bd[t-1]; bd[t-1] = td;
                    int   ti = bi[t]; bi[t] = bi[t-1]; bi[t-1] = ti;
                }
            }
        }
    }
    #pragma unroll
    for (int k = 0; k < KNN; k++) {
        smd[(quarter * 64 + qi) * KNN + k] = bd[k];
        smi[(quarter * 64 + qi) * KNN + k] = bi[k];
    }
    __syncthreads();

    if (threadIdx.x < 64) {
        // 4-way merge: ties broken toward the lowest quarter (lowest index)
        int head[4] = {0, 0, 0, 0};
        size_t base = (size_t)(b * NPTS + n) * KNN;
        #pragma unroll
        for (int k = 0; k < KNN; k++) {
            int bestq = 0;
            float bestd = smd[(0 * 64 + qi) * KNN + head[0]];
            #pragma unroll
            for (int qq = 1; qq < 4; qq++) {
                float dv = smd[(qq * 64 + qi) * KNN + head[qq]];
                if (dv < bestd) { bestd = dv; bestq = qq; }
            }
            idxOut[base + k] = smi[(bestq * 64 + qi) * KNN + head[bestq]];
            d2Out [base + k] = bestd;
            head[bestq]++;
        }
    }
}

__global__ __launch_bounds__(256) void topk_kernel(
    const float* __restrict__ q, int qbs,
    const float* __restrict__ s, int sbs,
    int*   __restrict__ idxOut,
    float* __restrict__ d2Out)
{
    __shared__ float sxs[NPTS], sys[NPTS], szs[NPTS];
    __shared__ float smd[4 * 64 * KNN];
    __shared__ int   smi[4 * 64 * KNN];
    topk_body4(q, qbs, s, sbs, blockIdx.x, idxOut, d2Out,
               sxs, sys, szs, smd, smi);
}

__global__ __launch_bounds__(256) void topk_pre_kernel(
    const float* __restrict__ frames)
{
    __shared__ float sxs[NPTS], sys[NPTS], szs[NPTS];
    __shared__ float smd[4 * 64 * KNN];
    __shared__ int   smi[4 * 64 * KNN];

    const int FBS = SEQ * NPTS * 3;
    const int FRM = NPTS * 3;
    int t = blockIdx.y;
    int qf = (t < 6) ? t : 5;
    int sf = (t == 0) ? 0 : ((t < 6) ? (t - 1) : 5);
    topk_body4(frames + qf * FRM, FBS, frames + sf * FRM, FBS, blockIdx.x,
               g_idx + (size_t)t * BNT * KNN, g_d2 + (size_t)t * BNT * KNN,
               sxs, sys, szs, smd, smi);
}

// ---------------------------------------------------------------------------
// FUSED combine1+combine2 (validated round 13)
// ---------------------------------------------------------------------------
__global__ __launch_bounds__(256) void combine12_kernel(
    const float* __restrict__ Z1,
    const float* __restrict__ Z2,
    const float* __restrict__ W1,
    const float* __restrict__ b1,
    const float* __restrict__ W2,
    const float* __restrict__ b2,
    const int*   __restrict__ idx,
    const float* __restrict__ d2,
    const float* __restrict__ qx, int qbs,
    float r2c1, float r2c2,
    bf16* __restrict__ f1oh, bf16* __restrict__ f1ol,
    bf16* __restrict__ f2oh, bf16* __restrict__ f2ol,
    const float* __restrict__ Wf2)
{
    __shared__ int    sRow1[8][KNN], sRow2[8][KNN];
    __shared__ float2 frow2[8][64];
    __shared__ float2 wn2[64][64];
    __shared__ float  sQ2[8][128];

    int tid = threadIdx.x;
    int p0 = blockIdx.x * 8;

    if (tid < 64) {
        int pt = tid >> 3, k = tid & 7;
        int p = p0 + pt;
        int b = p >> 9;
        int raw = idx[p * KNN + k];
        int i0  = idx[p * KNN];
        float dd = d2[p * KNN + k];
        sRow1[pt][k] = b * NPTS + ((dd <= r2c1) ? raw : i0);
        sRow2[pt][k] = b * NPTS + ((dd <= r2c2) ? raw : i0);
    }
    #pragma unroll 4
    for (int i = tid; i < 64 * 64; i += 256)
        reinterpret_cast<float2*>(wn2)[i] =
            reinterpret_cast<const float2*>(Wf2)[i];
    __syncthreads();

    int x = tid & 31, y = tid >> 5;
    {
        int p = p0 + y;
        int b = p >> 9, n = p & 511;
        int j0 = 2 * x;
        float2 w0 = *reinterpret_cast<const float2*>(&W1[j0]);
        float2 w1 = *reinterpret_cast<const float2*>(&W1[64 + j0]);
        float2 w2 = *reinterpret_cast<const float2*>(&W1[128 + j0]);
        float2 bb = *reinterpret_cast<const float2*>(&b1[j0]);

        const float* qp = qx + b * qbs + n * 3;
        float q0 = qp[0], q1 = qp[1], q2v = qp[2];
        float tx = q0 * w0.x + q1 * w1.x + q2v * w2.x;
        float ty = q0 * w0.y + q1 * w1.y + q2v * w2.y;

        float mx = -3.4e38f, my = -3.4e38f;
        #pragma unroll
        for (int k = 0; k < KNN; k++) {
            int row = sRow1[y][k];
            float2 zf = unpk(__ldg(reinterpret_cast<const ull*>(&Z1[(size_t)row * 64 + j0])));
            mx = fmaxf(mx, zf.x);
            my = fmaxf(my, zf.y);
        }
        float ox = bb.x + (mx - tx);
        float oy = bb.y + (my - ty);

        pack_store(f1oh, f1ol, (size_t)p * 64 + j0, ox, oy);

        frow2[y][j0]     = make_float2(ox, ox);
        frow2[y][j0 + 1] = make_float2(oy, oy);
    }
    __syncthreads();

    {
        ull a0 = 0ull, a1 = 0ull;
        #pragma unroll 8
        for (int c = 0; c < 64; c++) {
            ull f = *reinterpret_cast<const ull*>(&frow2[y][c]);
            ffma2(a0, f, *reinterpret_cast<const ull*>(&wn2[c][x]));
            ffma2(a1, f, *reinterpret_cast<const ull*>(&wn2[c][x + 32]));
        }
        float2 qo0 = unpk(a0), qo1 = unpk(a1);
        int j0 = 2 * x;
        sQ2[y][j0]          = qo0.x;
        sQ2[y][j0 + 1]      = qo0.y;
        sQ2[y][64 + j0]     = qo1.x;
        sQ2[y][64 + j0 + 1] = qo1.y;
    }
    __syncthreads();

    {
        int x2 = tid & 63, yg = tid >> 6;
        int j0 = 2 * x2;
        float2 w0 = *reinterpret_cast<const float2*>(&W2[j0]);
        float2 w1 = *reinterpret_cast<const float2*>(&W2[128 + j0]);
        float2 w2 = *reinterpret_cast<const float2*>(&W2[256 + j0]);
        float2 bb = *reinterpret_cast<const float2*>(&b2[j0]);

        #pragma unroll
        for (int pt = yg; pt < 8; pt += 4) {
            int p = p0 + pt;
            int b = p >> 9, n = p & 511;
            const float* qp = qx + b * qbs + n * 3;
            float q0 = qp[0], q1 = qp[1], q2v = qp[2];
            float tx = q0 * w0.x + q1 * w1.x + q2v * w2.x;
            float ty = q0 * w0.y + q1 * w1.y + q2v * w2.y;

            float mx = -3.4e38f, my = -3.4e38f;
            #pragma unroll
            for (int k = 0; k < KNN; k++) {
                int row = sRow2[pt][k];
                float2 zf = unpk(__ldg(reinterpret_cast<const ull*>(&Z2[(size_t)row * 128 + j0])));
                mx = fmaxf(mx, zf.x);
                my = fmaxf(my, zf.y);
            }
            float2 qv = *reinterpret_cast<const float2*>(&sQ2[pt][j0]);
            float ox = bb.x + qv.x + (mx - tx);
            float oy = bb.y + qv.y + (my - ty);
            pack_store(f2oh, f2ol, (size_t)p * 128 + j0, ox, oy);
        }
    }
}

// ---------------------------------------------------------------------------
// combine3 (validated round 13)
// ---------------------------------------------------------------------------
template<int C, int P>
__global__ __launch_bounds__((C/2)*P) void combine_kernel(
    const float* __restrict__ Z,
    const float* __restrict__ Qin,
    const float* __restrict__ W,
    const float* __restrict__ bias,
    const int*   __restrict__ idx,
    const float* __restrict__ d2,
    const float* __restrict__ qx, int qbs,
    float r2,
    bf16* __restrict__ outH,
    bf16* __restrict__ outL)
{
    __shared__ int sRow[P][KNN];

    int x = threadIdx.x, y = threadIdx.y;
    int p = blockIdx.x * P + y;
    int b = p >> 9, n = p & 511;

    if (x < KNN) {
        int   raw = idx[p * KNN + x];
        int   i0  = idx[p * KNN];
        float dd  = d2 [p * KNN + x];
        int eff = (dd <= r2) ? raw : i0;
        sRow[y][x] = b * NPTS + eff;
    }
    __syncthreads();

    int j0 = 2 * x;
    float2 w0 = *reinterpret_cast<const float2*>(&W[j0]);
    float2 w1 = *reinterpret_cast<const float2*>(&W[C + j0]);
    float2 w2 = *reinterpret_cast<const float2*>(&W[2*C + j0]);
    float2 bb = *reinterpret_cast<const float2*>(&bias[j0]);

    const float* qp = qx + b * qbs + n * 3;
    float q0 = qp[0], q1 = qp[1], q2v = qp[2];
    float tx = q0 * w0.x + q1 * w1.x + q2v * w2.x;
    float ty = q0 * w0.y + q1 * w1.y + q2v * w2.y;

    float mx = -3.4e38f, my = -3.4e38f;
    #pragma unroll
    for (int k = 0; k < KNN; k++) {
        int row = sRow[y][k];
        float2 zf = unpk(__ldg(reinterpret_cast<const ull*>(&Z[(size_t)row * C + j0])));
        mx = fmaxf(mx, zf.x);
        my = fmaxf(my, zf.y);
    }
    float2 qv = *reinterpret_cast<const float2*>(&Qin[(size_t)p * C + j0]);
    float ox = bb.x + qv.x + (mx - tx);
    float oy = bb.y + qv.y + (my - ty);
    pack_store(outH, outL, (size_t)p * C + j0, ox, oy);
}

// ---------------------------------------------------------------------------
// static stream/event setup
// ---------------------------------------------------------------------------
struct SideStream {
    cudaStream_t sB = nullptr;
    cudaEvent_t  evZ12 = nullptr, evZ3 = nullptr, evC12 = nullptr, evC3 = nullptr;
    bool ok = false;
    SideStream() {
        if (cudaStreamCreateWithFlags(&sB, cudaStreamNonBlocking) != cudaSuccess) return;
        cudaEventCreateWithFlags(&evZ12, cudaEventDisableTiming);
        cudaEventCreateWithFlags(&evZ3,  cudaEventDisableTiming);
        cudaEventCreateWithFlags(&evC12, cudaEventDisableTiming);
        cudaEventCreateWithFlags(&evC3,  cudaEventDisableTiming);
        noop_kernel<<<1, 1, 0, sB>>>();
        cudaEventRecord(evZ12, sB);
        cudaEventRecord(evZ3, sB);
        cudaEventRecord(evC12, sB);
        cudaEventRecord(evC3, sB);
        cudaStreamSynchronize(sB);
        ok = true;
    }
};
static SideStream g_ss;

// ---------------------------------------------------------------------------
// host orchestration
// ---------------------------------------------------------------------------
extern "C" void kernel_launch(void* const* d_in, const int* in_sizes, int n_in,
                              void* d_out, int out_size)
{
    (void)in_sizes; (void)n_in; (void)out_size;

    const float* frames = (const float*)d_in[0];
    const float* W1 = (const float*)d_in[1];
    const float* b1 = (const float*)d_in[2];
    const float* W2 = (const float*)d_in[3];
    const float* b2 = (const float*)d_in[4];
    const float* W3 = (const float*)d_in[5];
    const float* b3 = (const float*)d_in[6];
    const float* Wm = (const float*)d_in[7];
    const float* bm = (const float*)d_in[8];
    const float* Wl = (const float*)d_in[9];
    const float* bl = (const float*)d_in[10];
    float* out = (float*)d_out;

    bf16 *f1h, *f1l, *f2h, *f2l, *f3h, *f3l;
    float *Z1, *Z2, *Z3, *Q3;
    int* idxp; float* d2p;
    bf16 *wf3h, *wf3l, *wmh, *wml;
    { void* t;
      cudaGetSymbolAddress(&t, g_f1h); f1h = (bf16*)t;
      cudaGetSymbolAddress(&t, g_f1l); f1l = (bf16*)t;
      cudaGetSymbolAddress(&t, g_f2h); f2h = (bf16*)t;
      cudaGetSymbolAddress(&t, g_f2l); f2l = (bf16*)t;
      cudaGetSymbolAddress(&t, g_f3h); f3h = (bf16*)t;
      cudaGetSymbolAddress(&t, g_f3l); f3l = (bf16*)t;
      cudaGetSymbolAddress(&t, g_Z1); Z1 = (float*)t;
      cudaGetSymbolAddress(&t, g_Z2); Z2 = (float*)t;
      cudaGetSymbolAddress(&t, g_Z3); Z3 = (float*)t;
      cudaGetSymbolAddress(&t, g_Q3); Q3 = (float*)t;
      cudaGetSymbolAddress(&t, g_idx); idxp = (int*)t;
      cudaGetSymbolAddress(&t, g_d2);  d2p  = (float*)t;
      cudaGetSymbolAddress(&t, g_Wf3h); wf3h = (bf16*)t;
      cudaGetSymbolAddress(&t, g_Wf3l); wf3l = (bf16*)t;
      cudaGetSymbolAddress(&t, g_Wmh);  wmh  = (bf16*)t;
      cudaGetSymbolAddress(&t, g_Wml);  wml  = (bf16*)t;
    }

    cudaFuncSetAttribute(z12_kernel,
        cudaFuncAttributeMaxDynamicSharedMemorySize, DSMEM);
    cudaFuncSetAttribute(z3_kernel,
        cudaFuncAttributeMaxDynamicSharedMemorySize, DSMEM);
    cudaFuncSetAttribute(hmma_kernel,
        cudaFuncAttributeMaxDynamicSharedMemorySize, DSMEM);
    cudaFuncSetAttribute(hmma_mlp_kernel,
        cudaFuncAttributeMaxDynamicSharedMemorySize, DSMEM);

    const int FBS = SEQ * NPTS * 3;
    const int OBS = HALF * NPTS * 3;
    const int FRM = NPTS * 3;

    const double R0 = 4.0 + 1e-6, R1 = 8.0 + 1e-6, R2 = 12.0 + 1e-6;
    const float r2c1 = (float)(R0 * R0);
    const float r2c2 = (float)(R1 * R1);
    const float r2c3 = (float)(R2 * R2);

    const float* Wn1 = W1 + 3 * 64;
    const float* Wf2 = W2 + 3 * 128;
    const float* Wn2 = W2 + (3 + 64) * 128;
    const float* Wf3 = W3 + 3 * 256;
    const float* Wn3 = W3 + (3 + 128) * 256;

    init_kernel<<<512, 256>>>(Wn1, Wn2, Wn3, Wf3, Wm);
    topk_pre_kernel<<<dim3(128, 7), 256, 0, g_ss.sB>>>(frames);
    cudaEventRecord(g_ss.evC12, 0);
    cudaEventRecord(g_ss.evC3, 0);

    for (int t = 0; t < SEQ; t++) {
        const float *q, *s; int qbs, sbs;
        if (t < HALF) {
            q = frames + t * FRM;                       qbs = FBS;
            s = frames + (t ? (t - 1) : 0) * FRM;       sbs = FBS;
        } else if (t == HALF) {
            q = frames + (HALF - 1) * FRM;              qbs = FBS;
            s = q;                                      sbs = FBS;
        } else if (t == HALF + 1) {
            q = out;                                    qbs = OBS;
            s = frames + (HALF - 1) * FRM;              sbs = FBS;
        } else {
            q = out + (t - HALF - 1) * FRM;             qbs = OBS;
            s = out + (t - HALF - 2) * FRM;             sbs = OBS;
        }

        int pin = t & 1, pout = 1 - pin;
        bf16* f1ih = f1h + pin  * BNT * 64;
        bf16* f1il = f1l + pin  * BNT * 64;
        bf16* f1oh = f1h + pout * BNT * 64;
        bf16* f1ol = f1l + pout * BNT * 64;
        bf16* f2ih = f2h + pin  * BNT * 128;
        bf16* f2il = f2l + pin  * BNT * 128;
        bf16* f2oh = f2h + pout * BNT * 128;
        bf16* f2ol = f2l + pout * BNT * 128;
        bf16* f3ih = f3h + pin  * BNT * 256;
        bf16* f3il = f3l + pin  * BNT * 256;
        bf16* f3oh = f3h + pout * BNT * 256;
        bf16* f3ol = f3l + pout * BNT * 256;

        float* z1 = Z1 + (size_t)(t & 1) * BNT * 64;
        float* z2 = Z2 + (size_t)(t & 1) * BNT * 128;
        float* z3 = Z3 + (size_t)(t & 1) * BNT * 256;

        int slot = (t < 7) ? t : 7;
        int*   idxs = idxp + (size_t)slot * BNT * KNN;
        float* d2s  = d2p  + (size_t)slot * BNT * KNN;

        // ---- side stream: z12 gated on c12(t-1); z3 gated on c3(t-1) ----
        cudaStreamWaitEvent(g_ss.sB, g_ss.evC12, 0);
        z12_kernel<<<dim3(64, 3), 128, DSMEM, g_ss.sB>>>(
            f1ih, f1il, f2ih, f2il, W1, W2, s, sbs, z1, z2);
        cudaEventRecord(g_ss.evZ12, g_ss.sB);
        cudaStreamWaitEvent(g_ss.sB, g_ss.evC3, 0);
        z3_kernel<<<dim3(64, 4), 128, DSMEM, g_ss.sB>>>(
            f3ih, f3il, W3, s, sbs, z3);
        cudaEventRecord(g_ss.evZ3, g_ss.sB);

        // ---- main stream ----
        if (t >= 7)
            topk_kernel<<<128, 256>>>(q, qbs, s, sbs, idxs, d2s);

        cudaStreamWaitEvent(0, g_ss.evZ12, 0);

        combine12_kernel<<<BNT / 8, 256>>>(
            z1, z2, W1, b1, W2, b2, idxs, d2s, q, qbs, r2c1, r2c2,
            f1oh, f1ol, f2oh, f2ol, Wf2);
        cudaEventRecord(g_ss.evC12, 0);

        hmma_kernel<<<dim3(64, 4), 128, DSMEM>>>(
            f2oh, f2ol, wf3h, wf3l, Q3, 256, 128);

        cudaStreamWaitEvent(0, g_ss.evZ3, 0);

        combine_kernel<256, 2><<<BNT / 2, dim3(128, 2)>>>(
            z3, Q3, W3, b3, idxs, d2s, q, qbs, r2c3,
            f3oh, f3ol);
        cudaEventRecord(g_ss.evC3, 0);

        if (t >= HALF) {
            hmma_mlp_kernel<<<64, 128, DSMEM>>>(
                f3oh, f3ol, wmh, wml, 256,
                bm, Wl, bl, q, qbs, out + (t - HALF) * FRM, OBS);
        }
    }
}